// round 9
// baseline (speedup 1.0000x reference)
#include <cuda_runtime.h>
#include <cstdint>

#define Tn 4096   // B*S tokens
#define Dn 1024
#define En 8
#define Fn 4096
#define Bb 8
#define Sn 512

// ---------------- scratch (device globals; no allocations) ----------------
__device__ float g_lin[Tn * Dn];
__device__ float g_accb[Tn * Dn];          // x + moe accumulation
__device__ float g_h[2 * Tn * Fn];
__device__ float g_wc[Dn * En];            // folded gate: x@Wc = gate logits
__device__ float g_bc[En];
__device__ int   g_tok[2 * Tn];
__device__ float g_tw[2 * Tn];
__device__ int   g_cnt[En], g_off[En], g_fill[En];
__device__ int   g_gi[Tn * 2];
__device__ float g_gw[Tn * 2];
__device__ float g_sent[Bb * Dn];

// ---------------- helpers ----------------
__device__ __forceinline__ uint32_t s2u(const void* p) {
    uint32_t a;
    asm("{ .reg .u64 t; cvta.to.shared.u64 t, %1; cvt.u32.u64 %0, t; }" : "=r"(a) : "l"(p));
    return a;
}
__device__ __forceinline__ void mma8(float* c, const uint32_t* a,
                                     uint32_t b0, uint32_t b1) {
    asm volatile(
        "mma.sync.aligned.m16n8k8.row.col.f32.tf32.tf32.f32 "
        "{%0,%1,%2,%3},{%4,%5,%6,%7},{%8,%9},{%0,%1,%2,%3};"
        : "+f"(c[0]), "+f"(c[1]), "+f"(c[2]), "+f"(c[3])
        : "r"(a[0]), "r"(a[1]), "r"(a[2]), "r"(a[3]), "r"(b0), "r"(b1));
}
__device__ __forceinline__ void ldmx4(uint32_t* r, uint32_t a) {
    asm volatile("ldmatrix.sync.aligned.m8n8.x4.shared.b16 {%0,%1,%2,%3},[%4];"
                 : "=r"(r[0]), "=r"(r[1]), "=r"(r[2]), "=r"(r[3]) : "r"(a));
}
#define CPA(dst, src) \
    asm volatile("cp.async.cg.shared.global [%0], [%1], 16;" :: "r"(dst), "l"(src) : "memory")
#define CPCOMMIT() asm volatile("cp.async.commit_group;" ::: "memory")
#define CPWAIT0()  asm volatile("cp.async.wait_group 0;" ::: "memory")
#define CPWAIT1()  asm volatile("cp.async.wait_group 1;" ::: "memory")

// ---------------- Wc = W^T @ Wg (exact fp32), bc = b @ Wg ----------------
__global__ void __launch_bounds__(256) k_wc(const float* __restrict__ W,
                                            const float* __restrict__ Wg,
                                            const float* __restrict__ b) {
    __shared__ float swg[Dn * En];
    for (int i = threadIdx.x; i < Dn * En; i += 256) swg[i] = Wg[i];
    __syncthreads();
    int d = blockIdx.x * 256 + threadIdx.x;
    float acc[En] = {};
    for (int ep = 0; ep < Dn; ep++) {
        float wv = W[(size_t)ep * Dn + d];
        const float* wg = &swg[ep * En];
#pragma unroll
        for (int e = 0; e < En; e++) acc[e] += wv * wg[e];
    }
#pragma unroll
    for (int e = 0; e < En; e++) g_wc[d * En + e] = acc[e];
    if (blockIdx.x == 0 && threadIdx.x < En) {
        float s = 0.f;
        for (int ep = 0; ep < Dn; ep++) s += b[ep] * swg[ep * En + threadIdx.x];
        g_bc[threadIdx.x] = s;
    }
}

// ---------------- init: acc = x, zero counters ----------------
__global__ void k_init(const float* __restrict__ x) {
    if (blockIdx.x == 0 && threadIdx.x < En) g_cnt[threadIdx.x] = 0;
    int st = gridDim.x * blockDim.x;
    for (int i = blockIdx.x * blockDim.x + threadIdx.x; i < Tn * Dn; i += st)
        g_accb[i] = x[i];
}

// ---------------- gate from x via folded Wc (exact fp32 top-2) -------------
__global__ void k_gate2(const float* __restrict__ x) {
    int warp = (blockIdx.x * blockDim.x + threadIdx.x) >> 5;
    int lane = threadIdx.x & 31;
    if (warp >= Tn) return;
    const float* xr = &x[(size_t)warp * Dn];
    float p[En] = {};
    for (int i = lane; i < Dn; i += 32) {
        float v = xr[i];
        const float* w = &g_wc[i * En];
#pragma unroll
        for (int e = 0; e < En; e++) p[e] += v * w[e];
    }
#pragma unroll
    for (int o = 16; o; o >>= 1)
#pragma unroll
        for (int e = 0; e < En; e++) p[e] += __shfl_xor_sync(0xffffffffu, p[e], o);
    if (lane == 0) {
#pragma unroll
        for (int e = 0; e < En; e++) p[e] += g_bc[e];
        int i1 = 0;
        for (int e = 1; e < En; e++) if (p[e] > p[i1]) i1 = e;
        int i2 = -1;
        for (int e = 0; e < En; e++)
            if (e != i1 && (i2 < 0 || p[e] > p[i2])) i2 = e;
        float w1 = 1.f / (1.f + expf(p[i2] - p[i1]));
        g_gi[warp * 2] = i1; g_gi[warp * 2 + 1] = i2;
        g_gw[warp * 2] = w1; g_gw[warp * 2 + 1] = 1.f - w1;
        atomicAdd(&g_cnt[i1], 1);
        atomicAdd(&g_cnt[i2], 1);
    }
}

__global__ void k_off() {
    int a = 0;
    for (int e = 0; e < En; e++) { g_off[e] = a; a += g_cnt[e]; g_fill[e] = 0; }
}

__global__ void k_scatter() {
    int t = blockIdx.x * blockDim.x + threadIdx.x;
    if (t >= Tn) return;
#pragma unroll
    for (int k = 0; k < 2; k++) {
        int e = g_gi[t * 2 + k];
        int slot = g_off[e] + atomicAdd(&g_fill[e], 1);
        g_tok[slot] = t;
        g_tw[slot]  = g_gw[t * 2 + k];
    }
}

// ==== pipelined tf32 GEMM, ldmatrix feeds: 128x128 tile, Kc=32 =============
// MODE 0: g_lin = x @ W^T + b              (KD=Dn, NT=Dn; B=W[n][k], cp.async)
// MODE 1: g_h = relu(lin[g_tok]@w1[e]+b1)  (KD=Dn, NT=Fn; B=[k][n], transposed)
// MODE 2: g_accb += gw*(g_h@w2[e]+b2)      (KD=Fn, NT=Dn; B=[k][n], transposed)
template<int KD, int NT, int MODE>
__global__ void __launch_bounds__(256) pipe_ffn(const float* __restrict__ Asrc,
                                                const float* __restrict__ Bw,
                                                const float* __restrict__ bias)
{
    extern __shared__ float sm[];
    constexpr int STR = 36;                 // 144B rows: ldmatrix conflict-free
    constexpr uint32_t ASTG = 128 * STR * 4, BSTG = 128 * STR * 4;
    float* Asm = sm;                        // [2][128m][36k]
    float* Bsm = sm + 2 * 128 * STR;        // [2][128n][36k]

    int e = (MODE == 0) ? 0 : blockIdx.z;
    int cnt = (MODE == 0) ? Tn : g_cnt[e];
    int row0 = blockIdx.x * 128;
    if (MODE != 0 && row0 >= cnt) return;
    int off = (MODE == 0) ? 0 : g_off[e];
    int col0 = blockIdx.y * 128;
    int tid = threadIdx.x, warp = tid >> 5, lane = tid & 31;
    int warpM = warp >> 1, warpN = warp & 1;
    int grp = lane >> 2, tig = lane & 3;
    int mBase = warpM * 32, nBase = warpN * 64;

    uint32_t Au = s2u(Asm), Bu = s2u(Bsm);

    // ---- A staging: row ar, 16B chunks (cp.async) ----
    int ar = tid >> 1, ac = (tid & 1) * 16;
    const float* asrc;
    if (MODE == 0) {
        asrc = Asrc + (size_t)(row0 + ar) * KD;
    } else if (MODE == 1) {
        int r = row0 + ar;
        int tok = (r < cnt) ? g_tok[off + r] : g_tok[off];
        asrc = g_lin + (size_t)tok * KD;
    } else {
        int s = off + row0 + ar; if (s >= 2 * Tn) s = 0;
        asrc = g_h + (size_t)s * KD;
    }
    uint32_t aDst0 = Au + ((uint32_t)ar * STR + ac) * 4;

    // ---- B staging ----
    const float* bsrc;
    uint32_t bDst0 = 0;
    int bkr = 0, bn4 = 0;
    if (MODE == 0) {
        bsrc = Bw + (size_t)(col0 + ar) * KD;       // W[n][k], k contig
        bDst0 = Bu + ((uint32_t)ar * STR + ac) * 4;
    } else {
        bkr = tid >> 3; bn4 = (tid & 7) * 4;
        bsrc = Bw + (size_t)e * KD * NT + (size_t)bkr * NT + col0;
    }
    float4 breg[4];

    auto stageA = [&](int it) {
        int buf = it & 1;
        uint32_t ad = aDst0 + buf * ASTG;
        const float* as = asrc + it * 32 + ac;
#pragma unroll
        for (int j = 0; j < 4; j++) CPA(ad + j * 16, as + j * 4);
        if (MODE == 0) {
            uint32_t bd = bDst0 + buf * BSTG;
            const float* bs = bsrc + it * 32 + ac;
#pragma unroll
            for (int j = 0; j < 4; j++) CPA(bd + j * 16, bs + j * 4);
        }
        CPCOMMIT();
    };
    auto bload = [&](int it) {
        const float* bs = bsrc + (size_t)(it * 32) * NT;
#pragma unroll
        for (int j = 0; j < 4; j++) breg[j] = *(const float4*)(bs + bn4 + j * 32);
    };
    auto bsts = [&](int it) {
        int buf = it & 1;
        float* bb = Bsm + buf * 128 * STR;
#pragma unroll
        for (int j = 0; j < 4; j++) {
            int n = bn4 + j * 32;
            bb[(n + 0) * STR + bkr] = breg[j].x;
            bb[(n + 1) * STR + bkr] = breg[j].y;
            bb[(n + 2) * STR + bkr] = breg[j].z;
            bb[(n + 3) * STR + bkr] = breg[j].w;
        }
    };

    if (MODE != 0) { bload(0); bsts(0); }
    stageA(0);
    if (MODE != 0) bload(1);
    stageA(1);

    // ---- ldmatrix lane base addresses ----
    // A x4: reg0..3 = a0..a3 for m16k8 tile at (mBase+mt*16, ks)
    uint32_t aB0 = Au + (uint32_t)((mBase + (lane & 7) + 8 * ((lane >> 3) & 1)) * STR
                                   + 4 * (lane >> 4)) * 4;
    uint32_t aB1 = aB0 + 16 * STR * 4;
    // B x4: reg0,1 = b0,b1 (nt=2p); reg2,3 = b0,b1 (nt=2p+1)
    uint32_t bB[4];
#pragma unroll
    for (int p = 0; p < 4; p++)
        bB[p] = Bu + (uint32_t)((nBase + p * 16 + (lane & 7) + 8 * (lane >> 4)) * STR
                                + 4 * ((lane >> 3) & 1)) * 4;

    float cc[2][8][4] = {};
    constexpr int NK = KD / 32;
    for (int it = 0; it < NK; ++it) {
        if (it < NK - 1) { CPWAIT1(); } else { CPWAIT0(); }
        __syncthreads();
        uint32_t aOfs = (uint32_t)(it & 1) * ASTG, bOfs = (uint32_t)(it & 1) * BSTG;
#pragma unroll
        for (int ks = 0; ks < 32; ks += 8) {
            uint32_t af0[4], af1[4], bf[4][4];
            ldmx4(af0, aB0 + aOfs + ks * 4);
            ldmx4(af1, aB1 + aOfs + ks * 4);
#pragma unroll
            for (int p = 0; p < 4; p++) ldmx4(bf[p], bB[p] + bOfs + ks * 4);
#pragma unroll
            for (int p = 0; p < 4; p++) {
                mma8(cc[0][2 * p],     af0, bf[p][0], bf[p][1]);
                mma8(cc[0][2 * p + 1], af0, bf[p][2], bf[p][3]);
                mma8(cc[1][2 * p],     af1, bf[p][0], bf[p][1]);
                mma8(cc[1][2 * p + 1], af1, bf[p][2], bf[p][3]);
            }
        }
        __syncthreads();
        if (MODE != 0 && it + 1 < NK) bsts(it + 1);
        if (it + 2 < NK) {
            if (MODE != 0) bload(it + 2);
            stageA(it + 2);
        }
    }

    // ---- epilogue ----
#pragma unroll
    for (int mt = 0; mt < 2; mt++)
#pragma unroll
    for (int half = 0; half < 2; half++) {
        int r = row0 + mBase + mt * 16 + grp + half * 8;
        if (MODE != 0 && r >= cnt) continue;
        int slot = off + r;
        if (MODE == 0) {
            float* o = g_lin + (size_t)r * Dn + col0;
#pragma unroll
            for (int nt = 0; nt < 8; nt++) {
                int c = nBase + nt * 8 + 2 * tig;
                float2 v;
                v.x = cc[mt][nt][half * 2 + 0] + bias[col0 + c];
                v.y = cc[mt][nt][half * 2 + 1] + bias[col0 + c + 1];
                *(float2*)(o + c) = v;
            }
        } else if (MODE == 1) {
            float* o = g_h + (size_t)slot * Fn + col0;
#pragma unroll
            for (int nt = 0; nt < 8; nt++) {
                int c = nBase + nt * 8 + 2 * tig;
                float2 v;
                v.x = fmaxf(cc[mt][nt][half * 2 + 0] + bias[e * Fn + col0 + c], 0.f);
                v.y = fmaxf(cc[mt][nt][half * 2 + 1] + bias[e * Fn + col0 + c + 1], 0.f);
                *(float2*)(o + c) = v;
            }
        } else {
            int tok = g_tok[slot];
            float gw = g_tw[slot];
            float* o = g_accb + (size_t)tok * Dn + col0;
#pragma unroll
            for (int nt = 0; nt < 8; nt++) {
                int c = nBase + nt * 8 + 2 * tig;
                atomicAdd(&o[c],     gw * (cc[mt][nt][half * 2 + 0] + bias[e * Dn + col0 + c]));
                atomicAdd(&o[c + 1], gw * (cc[mt][nt][half * 2 + 1] + bias[e * Dn + col0 + c + 1]));
            }
        }
    }
}

// ---------------- mean pool + loss ----------------
__global__ void k_sent(float* out) {
    int i = blockIdx.x * blockDim.x + threadIdx.x;
    if (i == 0) out[0] = 0.f;
    if (i >= Bb * Dn) return;
    int b = i >> 10, d = i & 1023;
    const float* p = &g_accb[(size_t)(b * Sn) * Dn + d];
    float s = 0.f;
    for (int si = 0; si < Sn; si++) s += p[si * Dn];
    g_sent[i] = s * (1.f / Sn);
}

__global__ void k_loss(const int* __restrict__ y, float* out) {
    int b = blockIdx.x, tid = threadIdx.x;
    __shared__ float red[256];
    const float* s = &g_sent[b * Dn];
    float m = -1e30f;
    for (int i = tid; i < Dn; i += 256) m = fmaxf(m, s[i]);
    red[tid] = m; __syncthreads();
    for (int o = 128; o; o >>= 1) {
        if (tid < o) red[tid] = fmaxf(red[tid], red[tid + o]);
        __syncthreads();
    }
    float mx = red[0]; __syncthreads();
    float sum = 0.f;
    for (int i = tid; i < Dn; i += 256) sum += expf(s[i] - mx);
    red[tid] = sum; __syncthreads();
    for (int o = 128; o; o >>= 1) {
        if (tid < o) red[tid] += red[tid + o];
        __syncthreads();
    }
    if (tid == 0)
        atomicAdd(out, -(s[y[b]] - (mx + logf(red[0]))) * (1.f / Bb));
}

// ---------------- launch ----------------
extern "C" void kernel_launch(void* const* d_in, const int* in_sizes, int n_in,
                              void* d_out, int out_size) {
    const float* x  = (const float*)d_in[0];
    const int*   y  = (const int*)d_in[1];
    const float* W  = (const float*)d_in[2];
    const float* bb = (const float*)d_in[3];
    const float* Wg = (const float*)d_in[4];
    const float* w1 = (const float*)d_in[5];
    const float* b1 = (const float*)d_in[6];
    const float* w2 = (const float*)d_in[7];
    const float* b2 = (const float*)d_in[8];
    float* out = (float*)d_out;

    constexpr int SMEMB = 4 * 128 * 36 * 4;  // 73728 B
    static int done = 0;
    if (!done) {
        cudaFuncSetAttribute((const void*)pipe_ffn<Dn, Dn, 0>,
                             cudaFuncAttributeMaxDynamicSharedMemorySize, SMEMB);
        cudaFuncSetAttribute((const void*)pipe_ffn<Dn, Fn, 1>,
                             cudaFuncAttributeMaxDynamicSharedMemorySize, SMEMB);
        cudaFuncSetAttribute((const void*)pipe_ffn<Fn, Dn, 2>,
                             cudaFuncAttributeMaxDynamicSharedMemorySize, SMEMB);
        done = 1;
    }

    k_wc<<<Dn / 256, 256>>>(W, Wg, bb);
    k_init<<<256, 256>>>(x);
    k_gate2<<<(Tn * 32) / 256, 256>>>(x);
    pipe_ffn<Dn, Dn, 0><<<dim3(Tn / 128, Dn / 128, 1), 256, SMEMB>>>(x, W, bb);
    k_off<<<1, 1>>>();
    k_scatter<<<Tn / 256, 256>>>();
    pipe_ffn<Dn, Fn, 1><<<dim3(Tn / 128, Fn / 128, En), 256, SMEMB>>>(nullptr, w1, b1);
    pipe_ffn<Fn, Dn, 2><<<dim3(Tn / 128, Dn / 128, En), 256, SMEMB>>>(nullptr, w2, b2);
    k_sent<<<(Bb * Dn + 255) / 256, 256>>>(out);
    k_loss<<<Bb, 256>>>(y, out);
}